// round 16
// baseline (speedup 1.0000x reference)
#include <cuda_runtime.h>
#include <cuda_bf16.h>
#include <cuda_fp16.h>
#include <math.h>
#include <cstdint>

#define NROWS 8192
#define DIM   512
#define TOPK  12
#define THETA 10.0f
#define NBLK  (NROWS / 128)          // 64 column blocks

// ---------------- device scratch (no allocation allowed) -------------------
__device__ __nv_bfloat16 g_hn[NROWS * DIM];                    // 8 MB normalized bf16
__device__ float g_cv[(size_t)NROWS * NBLK * TOPK];            // 25 MB candidate vals
__device__ int   g_ci[(size_t)NROWS * NBLK * TOPK];            // 25 MB candidate idxs

__device__ __forceinline__ uint32_t smem_u32(const void* p) {
    uint32_t a;
    asm("{ .reg .u64 t; cvta.to.shared.u64 t, %1; cvt.u32.u64 %0, t; }"
        : "=r"(a) : "l"(p));
    return a;
}
__device__ __forceinline__ void cp_async16(uint32_t dst, const void* src) {
    asm volatile("cp.async.cg.shared.global [%0], [%1], 16;" :: "r"(dst), "l"(src));
}
__device__ __forceinline__ void cp_commit() {
    asm volatile("cp.async.commit_group;" ::: "memory");
}
template <int N>
__device__ __forceinline__ void cp_wait() {
    asm volatile("cp.async.wait_group %0;" :: "n"(N) : "memory");
}
__device__ __forceinline__ void ldsm_x4(uint32_t* r, uint32_t addr) {
    asm volatile("ldmatrix.sync.aligned.m8n8.x4.shared.b16 {%0,%1,%2,%3}, [%4];"
                 : "=r"(r[0]), "=r"(r[1]), "=r"(r[2]), "=r"(r[3]) : "r"(addr));
}
__device__ __forceinline__ void mma16816(float* c, const uint32_t* a,
                                         uint32_t b0, uint32_t b1) {
    asm volatile(
        "mma.sync.aligned.m16n8k16.row.col.f32.bf16.bf16.f32 "
        "{%0,%1,%2,%3}, {%4,%5,%6,%7}, {%8,%9}, {%0,%1,%2,%3};"
        : "+f"(c[0]), "+f"(c[1]), "+f"(c[2]), "+f"(c[3])
        : "r"(a[0]), "r"(a[1]), "r"(a[2]), "r"(a[3]), "r"(b0), "r"(b1));
}

// sorted-insert into a descending top-12 list (strict >: earlier index wins ties)
__device__ __forceinline__ void ins12(float* v, int* ix, float val, int idx) {
    if (val > v[TOPK - 1]) {
        int p = TOPK - 1;
        #pragma unroll
        for (int s = TOPK - 1; s > 0; s--) {
            if (v[s - 1] < val) { v[s] = v[s - 1]; ix[s] = ix[s - 1]; p = s - 1; }
        }
        v[p] = val; ix[p] = idx;
    }
}

// ---------------------------------------------------------------------------
// Kernel 1: row L2 norms -> normalized bf16 rows
// ---------------------------------------------------------------------------
__global__ __launch_bounds__(256) void norm_kernel(const float* __restrict__ h) {
    int row = blockIdx.x;
    int tid = threadIdx.x;
    const float* hr = h + (size_t)row * DIM;

    float v0 = hr[tid];
    float v1 = hr[tid + 256];
    float s = v0 * v0 + v1 * v1;
    #pragma unroll
    for (int off = 16; off > 0; off >>= 1) s += __shfl_xor_sync(~0u, s, off);

    __shared__ float red[8];
    if ((tid & 31) == 0) red[tid >> 5] = s;
    __syncthreads();
    if (tid < 32) {
        float t = (tid < 8) ? red[tid] : 0.0f;
        #pragma unroll
        for (int off = 4; off > 0; off >>= 1) t += __shfl_xor_sync(~0u, t, off);
        if (tid == 0) red[0] = t;
    }
    __syncthreads();
    float inv = 1.0f / fmaxf(sqrtf(red[0]), 1e-8f);
    g_hn[(size_t)row * DIM + tid]       = __float2bfloat16(v0 * inv);
    g_hn[(size_t)row * DIM + tid + 256] = __float2bfloat16(v1 * inv);
}

// ---------------------------------------------------------------------------
// Kernel 2: Sim tile (HMMA bf16) + FUSED per-tile top-12 extraction.
//   Upper-triangular tiles; tile staged to smem fp32; row-side serves
//   (block I rows, cand blk J), col-side serves (block J rows, cand blk I).
// ---------------------------------------------------------------------------
#define KC 64                        // bf16 elems per chunk (128 B per row)
#define NITER (DIM / KC)             // 8
#define ROWB 144                     // smem row stride (128B data + 16B pad)
#define STAGE_BYTES (2 * 128 * ROWB) // 36864
#define GSMEM (3 * STAGE_BYTES)      // 110592  (>= 128*132*4 = 67584 for stage)
#define STP 132                      // fp32 stage row stride (132 = 4 mod 32 banks)

__device__ __forceinline__ void load_stage(uint32_t sbase, int buf, int c,
                                           int tid, int bm, int bn) {
    uint32_t sA = sbase + buf * STAGE_BYTES;
    uint32_t sB = sA + 128 * ROWB;
    const char* gb = (const char*)g_hn;
    #pragma unroll
    for (int p = 0; p < 4; p++) {
        int i = tid + p * 256;
        int row = i >> 3, seg = i & 7;
        size_t koff = ((size_t)c * KC + seg * 8) * 2;
        cp_async16(sA + row * ROWB + seg * 16, gb + (size_t)(bm + row) * DIM * 2 + koff);
        cp_async16(sB + row * ROWB + seg * 16, gb + (size_t)(bn + row) * DIM * 2 + koff);
    }
}

__global__ __launch_bounds__(256) void gemm_kernel() {
    const int I = blockIdx.y, J = blockIdx.x;
    if (J < I) return;
    const int bm = I * 128, bn = J * 128;

    extern __shared__ char smem[];
    const uint32_t sbase = smem_u32(smem);
    const int tid = threadIdx.x;
    const int lane = tid & 31;
    const int wid = tid >> 5;
    const int warpM = wid >> 2;
    const int warpN = wid & 3;

    float acc[4][4][4];
    #pragma unroll
    for (int mi = 0; mi < 4; mi++)
        #pragma unroll
        for (int ni = 0; ni < 4; ni++)
            #pragma unroll
            for (int q = 0; q < 4; q++) acc[mi][ni][q] = 0.0f;

    load_stage(sbase, 0, 0, tid, bm, bn); cp_commit();
    load_stage(sbase, 1, 1, tid, bm, bn); cp_commit();

    const uint32_t aLane = (uint32_t)((warpM * 64 + (lane & 15)) * ROWB + (lane >> 4) * 16);
    const uint32_t bLane = (uint32_t)(128 * ROWB + (warpN * 32 + (lane & 15)) * ROWB + (lane >> 4) * 16);

    for (int c = 0; c < NITER; c++) {
        if (c + 2 < NITER) cp_wait<1>(); else cp_wait<0>();
        __syncthreads();
        if (c + 2 < NITER) load_stage(sbase, (c + 2) % 3, c + 2, tid, bm, bn);
        cp_commit();

        const uint32_t sbuf = sbase + (c % 3) * STAGE_BYTES;
        #pragma unroll
        for (int ks = 0; ks < 4; ks++) {
            uint32_t a[4][4], b[2][4];
            #pragma unroll
            for (int mi = 0; mi < 4; mi++)
                ldsm_x4(a[mi], sbuf + aLane + mi * (16 * ROWB) + ks * 32);
            #pragma unroll
            for (int nj = 0; nj < 2; nj++)
                ldsm_x4(b[nj], sbuf + bLane + nj * (16 * ROWB) + ks * 32);
            #pragma unroll
            for (int mi = 0; mi < 4; mi++)
                #pragma unroll
                for (int ni = 0; ni < 4; ni++) {
                    const int nj = ni >> 1, hi = ni & 1;
                    mma16816(acc[mi][ni], a[mi], b[nj][hi ? 1 : 0], b[nj][hi ? 3 : 2]);
                }
        }
    }

    // ---- stage tile to smem fp32 (stage buffers are free now) ----
    __syncthreads();
    float* st = reinterpret_cast<float*>(smem);
    {
        const int rl = warpM * 64 + (lane >> 2);
        const int cl = warpN * 32 + (lane & 3) * 2;
        #pragma unroll
        for (int mi = 0; mi < 4; mi++)
            #pragma unroll
            for (int ni = 0; ni < 4; ni++) {
                const int r = rl + mi * 16;
                const int cc = cl + ni * 8;
                st[r * STP + cc]           = acc[mi][ni][0];
                st[r * STP + cc + 1]       = acc[mi][ni][1];
                st[(r + 8) * STP + cc]     = acc[mi][ni][2];
                st[(r + 8) * STP + cc + 1] = acc[mi][ni][3];
            }
    }
    __syncthreads();

    // ---- per-tile top-12 extraction ----
    float v[TOPK]; int ix[TOPK];
    #pragma unroll
    for (int k = 0; k < TOPK; k++) { v[k] = -INFINITY; ix[k] = 0x7FFFFFFF; }

    if (tid < 128) {
        // row side: row (bm + tid), candidate block J
        const float* rowp = st + tid * STP;
        #pragma unroll 4
        for (int c4 = 0; c4 < 32; c4++) {
            float4 q = *reinterpret_cast<const float4*>(rowp + c4 * 4);
            ins12(v, ix, q.x, bn + c4 * 4);
            ins12(v, ix, q.y, bn + c4 * 4 + 1);
            ins12(v, ix, q.z, bn + c4 * 4 + 2);
            ins12(v, ix, q.w, bn + c4 * 4 + 3);
        }
        const size_t base = ((size_t)(bm + tid) * NBLK + J) * TOPK;
        #pragma unroll
        for (int k = 0; k < TOPK; k++) { g_cv[base + k] = v[k]; g_ci[base + k] = ix[k]; }
    } else if (I != J) {
        // col side: row (bn + c), candidate block I (transposed view)
        const int cc = tid - 128;
        #pragma unroll 4
        for (int r = 0; r < 128; r++)
            ins12(v, ix, st[r * STP + cc], bm + r);
        const size_t base = ((size_t)(bn + cc) * NBLK + I) * TOPK;
        #pragma unroll
        for (int k = 0; k < TOPK; k++) { g_cv[base + k] = v[k]; g_ci[base + k] = ix[k]; }
    }
}

// ---------------------------------------------------------------------------
// Kernel 3: merge 64 blocks x 12 candidates -> top-12 -> softmax -> gather
// ---------------------------------------------------------------------------
__global__ __launch_bounds__(256) void merge_kernel(const float* __restrict__ h,
                                                    float* __restrict__ out) {
    int row = blockIdx.x;
    int tid = threadIdx.x;
    const float* cv = g_cv + (size_t)row * NBLK * TOPK;
    const int*   ci = g_ci + (size_t)row * NBLK * TOPK;

    float v[TOPK]; int ix[TOPK];
    #pragma unroll
    for (int k = 0; k < TOPK; k++) { v[k] = -INFINITY; ix[k] = 0x7FFFFFFF; }

    // 768 candidates, 3 per thread, block-ascending order (tie rule preserved)
    #pragma unroll
    for (int e = 0; e < 3; e++) {
        int c = tid * 3 + e;
        ins12(v, ix, cv[c], ci[c]);
    }

    __shared__ float sV[256][TOPK];
    __shared__ int   sI[256][TOPK];
    #pragma unroll
    for (int k = 0; k < TOPK; k++) { sV[tid][k] = v[k]; sI[tid][k] = ix[k]; }

    for (int stride = 128; stride > 0; stride >>= 1) {
        __syncthreads();
        if (tid < stride) {
            float mv[TOPK]; int mi[TOPK];
            int a = 0, b = 0;
            #pragma unroll
            for (int k = 0; k < TOPK; k++) {
                float va = sV[tid][a], vb = sV[tid + stride][b];
                int   ia = sI[tid][a], ib = sI[tid + stride][b];
                bool takeA = (va > vb) || (va == vb && ia < ib);
                if (takeA) { mv[k] = va; mi[k] = ia; a++; }
                else       { mv[k] = vb; mi[k] = ib; b++; }
            }
            #pragma unroll
            for (int k = 0; k < TOPK; k++) { sV[tid][k] = mv[k]; sI[tid][k] = mi[k]; }
        }
    }
    __syncthreads();

    __shared__ float sBeta[TOPK];
    __shared__ int   sIdx[TOPK];
    if (tid == 0) {
        float m = sV[0][0];
        float e[TOPK], sum = 0.0f;
        #pragma unroll
        for (int k = 0; k < TOPK; k++) { e[k] = expf(THETA * (sV[0][k] - m)); sum += e[k]; }
        float inv = 1.0f / sum;
        #pragma unroll
        for (int k = 0; k < TOPK; k++) { sBeta[k] = e[k] * inv; sIdx[k] = sI[0][k]; }
    }
    __syncthreads();

    float beta[TOPK]; const float* hp[TOPK];
    #pragma unroll
    for (int k = 0; k < TOPK; k++) { beta[k] = sBeta[k]; hp[k] = h + (size_t)sIdx[k] * DIM; }

    #pragma unroll
    for (int d = tid; d < DIM; d += 256) {
        float acc = 0.0f;
        #pragma unroll
        for (int k = 0; k < TOPK; k++) acc += beta[k] * hp[k][d];
        out[(size_t)row * DIM + d] = acc;
    }
}

// ---------------------------------------------------------------------------
extern "C" void kernel_launch(void* const* d_in, const int* in_sizes, int n_in,
                              void* d_out, int out_size) {
    const float* h = (const float*)d_in[0];
    float* out = (float*)d_out;

    cudaFuncSetAttribute(gemm_kernel, cudaFuncAttributeMaxDynamicSharedMemorySize, GSMEM);

    norm_kernel<<<NROWS, 256>>>(h);
    gemm_kernel<<<dim3(NROWS / 128, NROWS / 128), 256, GSMEM>>>();
    merge_kernel<<<NROWS, 256>>>(h, out);
}

// round 17
// speedup vs baseline: 4.5138x; 4.5138x over previous
#include <cuda_runtime.h>
#include <cuda_bf16.h>
#include <cuda_fp16.h>
#include <math.h>
#include <cstdint>

#define NROWS 8192
#define DIM   512
#define TOPK  12
#define THETA 10.0f

// ---------------- device scratch (no allocation allowed) -------------------
__device__ __nv_bfloat16 g_hn[NROWS * DIM];              // 8 MB normalized bf16
__device__ __half g_sim[(size_t)NROWS * NROWS];          // 128 MB similarity

__device__ __forceinline__ uint32_t smem_u32(const void* p) {
    uint32_t a;
    asm("{ .reg .u64 t; cvta.to.shared.u64 t, %1; cvt.u32.u64 %0, t; }"
        : "=r"(a) : "l"(p));
    return a;
}
__device__ __forceinline__ void cp_async16(uint32_t dst, const void* src) {
    asm volatile("cp.async.cg.shared.global [%0], [%1], 16;" :: "r"(dst), "l"(src));
}
__device__ __forceinline__ void cp_commit() {
    asm volatile("cp.async.commit_group;" ::: "memory");
}
template <int N>
__device__ __forceinline__ void cp_wait() {
    asm volatile("cp.async.wait_group %0;" :: "n"(N) : "memory");
}
__device__ __forceinline__ void ldsm_x4(uint32_t* r, uint32_t addr) {
    asm volatile("ldmatrix.sync.aligned.m8n8.x4.shared.b16 {%0,%1,%2,%3}, [%4];"
                 : "=r"(r[0]), "=r"(r[1]), "=r"(r[2]), "=r"(r[3]) : "r"(addr));
}
__device__ __forceinline__ void mma16816(float* c, const uint32_t* a,
                                         uint32_t b0, uint32_t b1) {
    asm volatile(
        "mma.sync.aligned.m16n8k16.row.col.f32.bf16.bf16.f32 "
        "{%0,%1,%2,%3}, {%4,%5,%6,%7}, {%8,%9}, {%0,%1,%2,%3};"
        : "+f"(c[0]), "+f"(c[1]), "+f"(c[2]), "+f"(c[3])
        : "r"(a[0]), "r"(a[1]), "r"(a[2]), "r"(a[3]), "r"(b0), "r"(b1));
}

// ---------------------------------------------------------------------------
// Kernel 1: row L2 norms -> normalized bf16 rows
// ---------------------------------------------------------------------------
__global__ __launch_bounds__(256) void norm_kernel(const float* __restrict__ h) {
    int row = blockIdx.x;
    int tid = threadIdx.x;
    const float* hr = h + (size_t)row * DIM;

    float v0 = hr[tid];
    float v1 = hr[tid + 256];
    float s = v0 * v0 + v1 * v1;
    #pragma unroll
    for (int off = 16; off > 0; off >>= 1) s += __shfl_xor_sync(~0u, s, off);

    __shared__ float red[8];
    if ((tid & 31) == 0) red[tid >> 5] = s;
    __syncthreads();
    if (tid < 32) {
        float t = (tid < 8) ? red[tid] : 0.0f;
        #pragma unroll
        for (int off = 4; off > 0; off >>= 1) t += __shfl_xor_sync(~0u, t, off);
        if (tid == 0) red[0] = t;
    }
    __syncthreads();
    float inv = 1.0f / fmaxf(sqrtf(red[0]), 1e-8f);
    g_hn[(size_t)row * DIM + tid]       = __float2bfloat16(v0 * inv);
    g_hn[(size_t)row * DIM + tid + 256] = __float2bfloat16(v1 * inv);
}

// ---------------------------------------------------------------------------
// Kernel 2: Sim = hn @ hn^T, upper-triangular tiles, HMMA bf16.
//   Epilogue stages tile (normal + transposed) in smem fp16, then writes
//   BOTH directions as coalesced 16B stores (kills sector amplification).
// ---------------------------------------------------------------------------
#define KC 64                        // bf16 elems per chunk (128 B per row)
#define NITER (DIM / KC)             // 8
#define ROWB 144                     // smem row stride (128B data + 16B pad)
#define STAGE_BYTES (2 * 128 * ROWB) // 36864
#define GSMEM (3 * STAGE_BYTES)      // 110592 (epilogue needs 2*128*272=69632)
#define STR 136                      // fp16 stage row stride in halfs (272 B)

__device__ __forceinline__ void load_stage(uint32_t sbase, int buf, int c,
                                           int tid, int bm, int bn) {
    uint32_t sA = sbase + buf * STAGE_BYTES;
    uint32_t sB = sA + 128 * ROWB;
    const char* gb = (const char*)g_hn;
    #pragma unroll
    for (int p = 0; p < 4; p++) {
        int i = tid + p * 256;
        int row = i >> 3, seg = i & 7;
        size_t koff = ((size_t)c * KC + seg * 8) * 2;
        cp_async16(sA + row * ROWB + seg * 16, gb + (size_t)(bm + row) * DIM * 2 + koff);
        cp_async16(sB + row * ROWB + seg * 16, gb + (size_t)(bn + row) * DIM * 2 + koff);
    }
}

__global__ __launch_bounds__(256) void gemm_kernel() {
    const int I = blockIdx.y, J = blockIdx.x;
    if (J < I) return;
    const int bm = I * 128, bn = J * 128;

    extern __shared__ char smem[];
    const uint32_t sbase = smem_u32(smem);
    const int tid = threadIdx.x;
    const int lane = tid & 31;
    const int wid = tid >> 5;
    const int warpM = wid >> 2;
    const int warpN = wid & 3;

    float acc[4][4][4];
    #pragma unroll
    for (int mi = 0; mi < 4; mi++)
        #pragma unroll
        for (int ni = 0; ni < 4; ni++)
            #pragma unroll
            for (int q = 0; q < 4; q++) acc[mi][ni][q] = 0.0f;

    load_stage(sbase, 0, 0, tid, bm, bn); cp_commit();
    load_stage(sbase, 1, 1, tid, bm, bn); cp_commit();

    const uint32_t aLane = (uint32_t)((warpM * 64 + (lane & 15)) * ROWB + (lane >> 4) * 16);
    const uint32_t bLane = (uint32_t)(128 * ROWB + (warpN * 32 + (lane & 15)) * ROWB + (lane >> 4) * 16);

    for (int c = 0; c < NITER; c++) {
        if (c + 2 < NITER) cp_wait<1>(); else cp_wait<0>();
        __syncthreads();
        if (c + 2 < NITER) load_stage(sbase, (c + 2) % 3, c + 2, tid, bm, bn);
        cp_commit();

        const uint32_t sbuf = sbase + (c % 3) * STAGE_BYTES;
        #pragma unroll
        for (int ks = 0; ks < 4; ks++) {
            uint32_t a[4][4], b[2][4];
            #pragma unroll
            for (int mi = 0; mi < 4; mi++)
                ldsm_x4(a[mi], sbuf + aLane + mi * (16 * ROWB) + ks * 32);
            #pragma unroll
            for (int nj = 0; nj < 2; nj++)
                ldsm_x4(b[nj], sbuf + bLane + nj * (16 * ROWB) + ks * 32);
            #pragma unroll
            for (int mi = 0; mi < 4; mi++)
                #pragma unroll
                for (int ni = 0; ni < 4; ni++) {
                    const int nj = ni >> 1, hi = ni & 1;
                    mma16816(acc[mi][ni], a[mi], b[nj][hi ? 1 : 0], b[nj][hi ? 3 : 2]);
                }
        }
    }

    // ---- epilogue: stage fp16 tile (normal + transposed), coalesced out ----
    __syncthreads();                     // stage buffers free now
    __half* shN = reinterpret_cast<__half*>(smem);
    __half* shT = shN + 128 * STR;
    const bool offdiag = (I != J);
    {
        const int rl = warpM * 64 + (lane >> 2);
        const int cl = warpN * 32 + (lane & 3) * 2;
        #pragma unroll
        for (int mi = 0; mi < 4; mi++)
            #pragma unroll
            for (int ni = 0; ni < 4; ni++) {
                const int r = rl + mi * 16;
                const int cc = cl + ni * 8;
                __half d0 = __float2half_rn(acc[mi][ni][0]);
                __half d1 = __float2half_rn(acc[mi][ni][1]);
                __half d2 = __float2half_rn(acc[mi][ni][2]);
                __half d3 = __float2half_rn(acc[mi][ni][3]);
                *reinterpret_cast<__half2*>(shN + r * STR + cc)       = make_half2(d0, d1);
                *reinterpret_cast<__half2*>(shN + (r + 8) * STR + cc) = make_half2(d2, d3);
                if (offdiag) {
                    shT[cc * STR + r]           = d0;
                    shT[(cc + 1) * STR + r]     = d1;
                    shT[cc * STR + r + 8]       = d2;
                    shT[(cc + 1) * STR + r + 8] = d3;
                }
            }
    }
    __syncthreads();

    // coalesced writeback: each thread one 128B half-row segment per direction
    {
        const int rr = tid >> 1, seg = tid & 1;
        const uint4* srcN = reinterpret_cast<const uint4*>(shN + rr * STR + seg * 64);
        uint4* dstN = reinterpret_cast<uint4*>(g_sim + (size_t)(bm + rr) * NROWS + bn + seg * 64);
        #pragma unroll
        for (int i = 0; i < 8; i++) dstN[i] = srcN[i];
        if (offdiag) {
            const uint4* srcT = reinterpret_cast<const uint4*>(shT + rr * STR + seg * 64);
            uint4* dstT = reinterpret_cast<uint4*>(g_sim + (size_t)(bn + rr) * NROWS + bm + seg * 64);
            #pragma unroll
            for (int i = 0; i < 8; i++) dstT[i] = srcT[i];
        }
    }
}

// ---------------------------------------------------------------------------
// Kernel 3: per-row top-12 (fp16 sims) -> softmax -> weighted gather of h
// ---------------------------------------------------------------------------
__global__ __launch_bounds__(256) void topk_kernel(const float* __restrict__ h,
                                                   float* __restrict__ out) {
    int row = blockIdx.x;
    int tid = threadIdx.x;
    const __half* sim = g_sim + (size_t)row * NROWS;

    float v[TOPK]; int ix[TOPK];
    #pragma unroll
    for (int k = 0; k < TOPK; k++) { v[k] = -INFINITY; ix[k] = 0x7FFFFFFF; }

    #pragma unroll
    for (int t = 0; t < 4; t++) {
        int base8 = t * 256 + tid;               // uint4 index (8 halfs)
        uint4 u = reinterpret_cast<const uint4*>(sim)[base8];
        int j0 = base8 * 8;
        uint32_t w[4] = {u.x, u.y, u.z, u.w};
        #pragma unroll
        for (int e = 0; e < 8; e++) {
            __half hv = ((const __half*)w)[e];
            float val = __half2float(hv);
            if (val > v[TOPK - 1]) {
                int p = TOPK - 1;
                #pragma unroll
                for (int s = TOPK - 1; s > 0; s--) {
                    if (v[s - 1] < val) { v[s] = v[s - 1]; ix[s] = ix[s - 1]; p = s - 1; }
                }
                v[p] = val; ix[p] = j0 + e;
            }
        }
    }

    __shared__ float sV[256][TOPK];
    __shared__ int   sI[256][TOPK];
    #pragma unroll
    for (int k = 0; k < TOPK; k++) { sV[tid][k] = v[k]; sI[tid][k] = ix[k]; }

    for (int stride = 128; stride > 0; stride >>= 1) {
        __syncthreads();
        if (tid < stride) {
            float mv[TOPK]; int mi[TOPK];
            int a = 0, b = 0;
            #pragma unroll
            for (int k = 0; k < TOPK; k++) {
                float va = sV[tid][a], vb = sV[tid + stride][b];
                int   ia = sI[tid][a], ib = sI[tid + stride][b];
                bool takeA = (va > vb) || (va == vb && ia < ib);
                if (takeA) { mv[k] = va; mi[k] = ia; a++; }
                else       { mv[k] = vb; mi[k] = ib; b++; }
            }
            #pragma unroll
            for (int k = 0; k < TOPK; k++) { sV[tid][k] = mv[k]; sI[tid][k] = mi[k]; }
        }
    }
    __syncthreads();

    __shared__ float sBeta[TOPK];
    __shared__ int   sIdx[TOPK];
    if (tid == 0) {
        float m = sV[0][0];
        float e[TOPK], sum = 0.0f;
        #pragma unroll
        for (int k = 0; k < TOPK; k++) { e[k] = expf(THETA * (sV[0][k] - m)); sum += e[k]; }
        float inv = 1.0f / sum;
        #pragma unroll
        for (int k = 0; k < TOPK; k++) { sBeta[k] = e[k] * inv; sIdx[k] = sI[0][k]; }
    }
    __syncthreads();

    float beta[TOPK]; const float* hp[TOPK];
    #pragma unroll
    for (int k = 0; k < TOPK; k++) { beta[k] = sBeta[k]; hp[k] = h + (size_t)sIdx[k] * DIM; }

    #pragma unroll
    for (int d = tid; d < DIM; d += 256) {
        float acc = 0.0f;
        #pragma unroll
        for (int k = 0; k < TOPK; k++) acc += beta[k] * hp[k][d];
        out[(size_t)row * DIM + d] = acc;
    }
}

// ---------------------------------------------------------------------------
extern "C" void kernel_launch(void* const* d_in, const int* in_sizes, int n_in,
                              void* d_out, int out_size) {
    const float* h = (const float*)d_in[0];
    float* out = (float*)d_out;

    cudaFuncSetAttribute(gemm_kernel, cudaFuncAttributeMaxDynamicSharedMemorySize, GSMEM);

    norm_kernel<<<NROWS, 256>>>(h);
    gemm_kernel<<<dim3(NROWS / 128, NROWS / 128), 256, GSMEM>>>();
    topk_kernel<<<NROWS, 256>>>(h, out);
}